// round 1
// baseline (speedup 1.0000x reference)
#include <cuda_runtime.h>
#include <cstdint>

#define D_IN      64
#define LATENT    512
#define KSEL      32
#define CHUNK     16
#define NTHREADS  512
#define DEC_STRIDE 66   // padded transposed dec_W stride (floats) -> conflict-free LDS.64

typedef unsigned long long ull;

__device__ __forceinline__ ull pack2(float lo, float hi) {
    ull r; asm("mov.b64 %0, {%1,%2};" : "=l"(r) : "f"(lo), "f"(hi)); return r;
}
__device__ __forceinline__ void unpack2(ull v, float& lo, float& hi) {
    asm("mov.b64 {%0,%1}, %2;" : "=f"(lo), "=f"(hi) : "l"(v));
}
// packed dual fp32 FMA (Blackwell f32x2 pipe, 2x FFMA throughput)
__device__ __forceinline__ ull fma2(ull a, ull b, ull c) {
    ull d; asm("fma.rn.f32x2 %0, %1, %2, %3;" : "=l"(d) : "l"(a), "l"(b), "l"(c)); return d;
}

__global__ void __launch_bounds__(NTHREADS, 1)
sae_fused_kernel(const float* __restrict__ x,
                 const float* __restrict__ encW,
                 const float* __restrict__ encb,
                 const float* __restrict__ decW,
                 const float* __restrict__ decb,
                 float* __restrict__ outx,
                 float* __restrict__ outz,
                 int nChunks)
{
    extern __shared__ float smem[];
    float* decT = smem;                               // LATENT * DEC_STRIDE
    float* xs   = smem + LATENT * DEC_STRIDE;         // CHUNK * D_IN
    float* zsh  = xs + CHUNK * D_IN;                  // CHUNK * LATENT

    const int tid  = threadIdx.x;
    const int lane = tid & 31;
    const int wid  = tid >> 5;
    const unsigned FULL = 0xffffffffu;
    const unsigned ltmask = (1u << lane) - 1u;

    // ---- one-time: transpose dec_W [64,512] -> decT[l][d] (padded stride) ----
    for (int i = tid; i < D_IN * LATENT; i += NTHREADS) {
        int d = i >> 9;              // row of dec_W (output dim)
        int l = i & (LATENT - 1);    // col (latent)
        decT[l * DEC_STRIDE + d] = decW[i];
    }

    // ---- one-time: encoder weight row for this thread's latent into f32x2 regs ----
    ull w2[32];
    {
        const float4* wr = reinterpret_cast<const float4*>(encW + tid * D_IN);
        #pragma unroll
        for (int g = 0; g < 16; g++) {
            float4 v = wr[g];
            w2[2 * g]     = pack2(v.x, v.y);
            w2[2 * g + 1] = pack2(v.z, v.w);
        }
    }
    const float bl  = encb[tid];
    const float db0 = decb[2 * lane];
    const float db1 = decb[2 * lane + 1];
    __syncthreads();

    for (int chunk = blockIdx.x; chunk < nChunks; chunk += gridDim.x) {
        const long long row0 = (long long)chunk * CHUNK;

        // ---- stage x chunk: 16 rows x 64 floats ----
        {
            const float2* gx = reinterpret_cast<const float2*>(x + row0 * D_IN);
            reinterpret_cast<float2*>(xs)[tid] = gx[tid];
        }
        __syncthreads();

        // ---- encoder GEMV: z[r][tid] = relu(dot(w_tid, x_r) + b) ----
        {
            const ulonglong2* xsu = reinterpret_cast<const ulonglong2*>(xs);
            #pragma unroll
            for (int rb = 0; rb < CHUNK; rb += 4) {
                ull a0 = 0, a1 = 0, a2 = 0, a3 = 0;
                #pragma unroll
                for (int g = 0; g < 16; g++) {
                    ulonglong2 x0 = xsu[(rb + 0) * 16 + g];
                    ulonglong2 x1 = xsu[(rb + 1) * 16 + g];
                    ulonglong2 x2 = xsu[(rb + 2) * 16 + g];
                    ulonglong2 x3 = xsu[(rb + 3) * 16 + g];
                    a0 = fma2(w2[2 * g], x0.x, a0); a0 = fma2(w2[2 * g + 1], x0.y, a0);
                    a1 = fma2(w2[2 * g], x1.x, a1); a1 = fma2(w2[2 * g + 1], x1.y, a1);
                    a2 = fma2(w2[2 * g], x2.x, a2); a2 = fma2(w2[2 * g + 1], x2.y, a2);
                    a3 = fma2(w2[2 * g], x3.x, a3); a3 = fma2(w2[2 * g + 1], x3.y, a3);
                }
                float lo, hi;
                unpack2(a0, lo, hi); zsh[(rb + 0) * LATENT + tid] = fmaxf(lo + hi + bl, 0.0f);
                unpack2(a1, lo, hi); zsh[(rb + 1) * LATENT + tid] = fmaxf(lo + hi + bl, 0.0f);
                unpack2(a2, lo, hi); zsh[(rb + 2) * LATENT + tid] = fmaxf(lo + hi + bl, 0.0f);
                unpack2(a3, lo, hi); zsh[(rb + 3) * LATENT + tid] = fmaxf(lo + hi + bl, 0.0f);
            }
        }
        __syncthreads();

        // ---- per-warp: exact top-32 of row `wid`, write z_sparse, decode x_hat ----
        {
            const int r = wid;
            const long long row = row0 + r;

            float va[16];
            #pragma unroll
            for (int j = 0; j < 16; j++) va[j] = zsh[r * LATENT + lane + 32 * j];

            // stats for warm-start guess (values are >=0 post-relu)
            float s = 0.0f, mx = 0.0f;
            #pragma unroll
            for (int j = 0; j < 16; j++) { s += va[j]; mx = fmaxf(mx, va[j]); }
            #pragma unroll
            for (int off = 16; off > 0; off >>= 1) {
                s  += __shfl_xor_sync(FULL, s, off);
                mx  = fmaxf(mx, __shfl_xor_sync(FULL, mx, off));
            }

            unsigned T;          // bit pattern of 32nd-largest value
            unsigned ge_cnt;     // count(v >= T)
            const unsigned mxu = __float_as_uint(mx);

            if (mxu == 0u) {
                T = 0u; ge_cnt = 512u;   // degenerate all-zero row
            } else {
                unsigned lo = 0u, hi = mxu + 1u;
                unsigned lo_c = 512u, hi_c = 0u;
                // Gaussian-quantile warm start: sigma from relu-mean, 32/512 tail
                float sigma = (s * (1.0f / 512.0f)) * 2.5066283f;
                unsigned m = __float_as_uint(1.5341f * sigma);
                if (m <= lo) m = lo + 1u;
                if (m >= hi) m = hi - 1u;

                int iter = 0;
                T = 0u; ge_cnt = 512u;
                while (true) {
                    int c = 0;
                    #pragma unroll
                    for (int j = 0; j < 16; j++) c += (__float_as_uint(va[j]) >= m);
                    c = __reduce_add_sync(FULL, c);

                    if (c == KSEL) {                 // exact bracket: T = min of survivors
                        unsigned tmin = 0xffffffffu;
                        #pragma unroll
                        for (int j = 0; j < 16; j++) {
                            unsigned u = __float_as_uint(va[j]);
                            if (u >= m) tmin = min(tmin, u);
                        }
                        T = __reduce_min_sync(FULL, tmin);
                        ge_cnt = KSEL;
                        break;
                    }
                    if (c > KSEL) { lo = m; lo_c = (unsigned)c; }
                    else          { hi = m; hi_c = (unsigned)c; }
                    if (hi - lo <= 1u) { T = lo; ge_cnt = lo_c; break; }

                    iter++;
                    if (iter & 1) {
                        m = lo + ((hi - lo) >> 1);   // guaranteed-progress bisection
                    } else {
                        // log-count interpolation (tail ~ exponential in value)
                        float fl = __uint_as_float(lo), fh = __uint_as_float(hi);
                        float lc = __logf((float)lo_c);
                        float hc = __logf((float)max(hi_c, 1u));
                        float t  = (lc - 3.4657359f) / fmaxf(lc - hc, 1e-6f); // ln(32)=3.4657
                        float mf = fl + t * (fh - fl);
                        unsigned mm = __float_as_uint(mf);
                        if (!(mf > fl && mf < fh)) mm = lo + ((hi - lo) >> 1);
                        m = mm;
                        if (m <= lo) m = lo + 1u;
                        if (m >= hi) m = hi - 1u;
                    }
                }
            }

            // ---- selection mask (stable ties by index, matching jax.lax.top_k) ----
            unsigned selmask = 0u;
            if (ge_cnt == KSEL) {
                #pragma unroll
                for (int j = 0; j < 16; j++)
                    if (__float_as_uint(va[j]) >= T) selmask |= 1u << j;
            } else {
                int gt = 0;
                #pragma unroll
                for (int j = 0; j < 16; j++) gt += (__float_as_uint(va[j]) > T);
                gt = __reduce_add_sync(FULL, gt);
                int need = KSEL - gt;
                int running = 0;
                #pragma unroll
                for (int j = 0; j < 16; j++) {
                    unsigned u = __float_as_uint(va[j]);
                    bool g = (u > T);
                    bool e = (u == T);
                    unsigned eb = __ballot_sync(FULL, e);
                    int rank = running + __popc(eb & ltmask);
                    running += __popc(eb);
                    if (g || (e && rank < need)) selmask |= 1u << j;
                }
            }

            // ---- write z_sparse row (coalesced: lane-contiguous per j) ----
            float* oz = outz + row * LATENT;
            #pragma unroll
            for (int j = 0; j < 16; j++)
                oz[lane + 32 * j] = ((selmask >> j) & 1u) ? va[j] : 0.0f;

            // ---- decode: x_hat = dec_b + sum_{sel} v * decT[idx][:] ----
            ull acc = pack2(db0, db1);
            #pragma unroll
            for (int j = 0; j < 16; j++) {
                unsigned bal = __ballot_sync(FULL, (selmask >> j) & 1u);
                while (bal) {
                    int src = __ffs(bal) - 1;
                    bal &= bal - 1u;
                    float v = __shfl_sync(FULL, va[j], src);
                    int idx = src + 32 * j;
                    ull v2 = pack2(v, v);
                    ull dp = *reinterpret_cast<const ull*>(decT + idx * DEC_STRIDE + 2 * lane);
                    acc = fma2(v2, dp, acc);
                }
            }
            float o0, o1;
            unpack2(acc, o0, o1);
            float2 ov; ov.x = o0; ov.y = o1;
            *reinterpret_cast<float2*>(outx + row * D_IN + 2 * lane) = ov;
        }
        __syncthreads();   // protect xs/zsh before next chunk overwrites them
    }
}

extern "C" void kernel_launch(void* const* d_in, const int* in_sizes, int n_in,
                              void* d_out, int out_size)
{
    const float* x    = (const float*)d_in[0];
    const float* encW = (const float*)d_in[1];
    const float* encb = (const float*)d_in[2];
    const float* decW = (const float*)d_in[3];
    const float* decb = (const float*)d_in[4];

    const int B = in_sizes[0] / D_IN;
    float* outx = (float*)d_out;                       // x_hat [B, 64]
    float* outz = (float*)d_out + (size_t)B * D_IN;    // z_sparse [B, 512]

    const int nChunks = B / CHUNK;
    const size_t shmem = (size_t)(LATENT * DEC_STRIDE + CHUNK * D_IN + CHUNK * LATENT) * sizeof(float);

    cudaFuncSetAttribute(sae_fused_kernel, cudaFuncAttributeMaxDynamicSharedMemorySize, (int)shmem);

    sae_fused_kernel<<<148, NTHREADS, shmem>>>(x, encW, encb, decW, decb, outx, outz, nChunks);
}

// round 3
// speedup vs baseline: 1.2521x; 1.2521x over previous
#include <cuda_runtime.h>
#include <cstdint>

#define D_IN      64
#define LATENT    512
#define KSEL      32
#define CHUNK     16
#define NTHREADS  512
#define DEC_STRIDE 66   // padded transposed dec_W stride (floats) -> conflict-free LDS.64
#define GRID      148

typedef unsigned long long ull;

__device__ __forceinline__ ull pack2(float lo, float hi) {
    ull r; asm("mov.b64 %0, {%1,%2};" : "=l"(r) : "f"(lo), "f"(hi)); return r;
}
__device__ __forceinline__ void unpack2(ull v, float& lo, float& hi) {
    asm("mov.b64 {%0,%1}, %2;" : "=f"(lo), "=f"(hi) : "l"(v));
}
__device__ __forceinline__ ull fma2(ull a, ull b, ull c) {
    ull d; asm("fma.rn.f32x2 %0, %1, %2, %3;" : "=l"(d) : "l"(a), "l"(b), "l"(c)); return d;
}
__device__ __forceinline__ ull add2(ull a, ull b) {
    ull d; asm("add.rn.f32x2 %0, %1, %2;" : "=l"(d) : "l"(a), "l"(b)); return d;
}
__device__ __forceinline__ unsigned smem_u32(const void* p) {
    unsigned a; asm("{ .reg .u64 t; cvta.to.shared.u64 t, %1; cvt.u32.u64 %0, t; }" : "=r"(a) : "l"(p));
    return a;
}
__device__ __forceinline__ void cp_async8(unsigned dst, const void* src) {
    asm volatile("cp.async.ca.shared.global [%0], [%1], 8;" :: "r"(dst), "l"(src) : "memory");
}

// SMEM layout (floats):
//  decT : LATENT*DEC_STRIDE   (135168 B)
//  zsh  : 2 * CHUNK*LATENT    ( 65536 B)
//  xs   : 2 * CHUNK*D_IN      (  8192 B)
//  zsel : CHUNK*KSEL ulls     (  4096 B)
#define SM_DECT  0
#define SM_ZSH   (LATENT * DEC_STRIDE)
#define SM_XS    (SM_ZSH + 2 * CHUNK * LATENT)
#define SM_ZSEL  (SM_XS + 2 * CHUNK * D_IN)
#define SM_FLOATS (SM_ZSEL + 2 * CHUNK * KSEL)

__global__ void __launch_bounds__(NTHREADS, 1)
sae_fused_kernel(const float* __restrict__ x,
                 const float* __restrict__ encW,
                 const float* __restrict__ encb,
                 const float* __restrict__ decW,
                 const float* __restrict__ decb,
                 float* __restrict__ outx,
                 float* __restrict__ outz,
                 int nChunks)
{
    extern __shared__ float smem[];
    float* decT = smem + SM_DECT;
    float* zsh  = smem + SM_ZSH;
    float* xs   = smem + SM_XS;
    ull*   zsel = reinterpret_cast<ull*>(smem + SM_ZSEL);

    const int tid  = threadIdx.x;
    const int lane = tid & 31;
    const int wid  = tid >> 5;
    const unsigned FULL = 0xffffffffu;
    const unsigned ltmask = (1u << lane) - 1u;

    // ---- one-time: transpose dec_W [64,512] -> decT[l][d] (padded stride) ----
    for (int i = tid; i < D_IN * LATENT; i += NTHREADS) {
        int d = i >> 9;
        int l = i & (LATENT - 1);
        decT[l * DEC_STRIDE + d] = decW[i];
    }

    // ---- one-time: encoder weight row (latent = tid) into f32x2 registers ----
    ull w2[32];
    {
        const float4* wr = reinterpret_cast<const float4*>(encW + tid * D_IN);
        #pragma unroll
        for (int g = 0; g < 16; g++) {
            float4 v = wr[g];
            w2[2 * g]     = pack2(v.x, v.y);
            w2[2 * g + 1] = pack2(v.z, v.w);
        }
    }
    const float bl  = encb[tid];
    const float db0 = decb[2 * lane];
    const float db1 = decb[2 * lane + 1];

    // ---- prefetch x for first chunk into buffer 0 (distance-1 pipeline) ----
    int c0 = blockIdx.x;
    int buf = 0;                      // EXPLICIT per-iteration toggle (GRID is even -> (c&1) is constant!)
    if (c0 < nChunks) {
        unsigned dst = smem_u32(xs) + tid * 8;
        cp_async8(dst, x + (long long)c0 * (CHUNK * D_IN) + tid * 2);
    }
    asm volatile("cp.async.commit_group;" ::: "memory");

    for (int c = c0; c < nChunks; c += GRID) {
        const long long row0 = (long long)c * CHUNK;
        float* xsA  = xs  + buf * (CHUNK * D_IN);
        float* zshA = zsh + buf * (CHUNK * LATENT);

        // wait for this chunk's x prefetch; barrier also guarantees:
        //  - all threads done with topk(c-1) [zsh(prev buf) free]
        //  - all threads done with enc(c-1)  [xs(buf^1) free for prefetch below]
        asm volatile("cp.async.wait_group 0;" ::: "memory");
        __syncthreads();

        // prefetch chunk c+GRID into the OTHER xs buffer (overlaps enc+topk)
        {
            int cn = c + GRID;
            if (cn < nChunks) {
                unsigned dst = smem_u32(xs + (buf ^ 1) * (CHUNK * D_IN)) + tid * 8;
                cp_async8(dst, x + (long long)cn * (CHUNK * D_IN) + tid * 2);
            }
            asm volatile("cp.async.commit_group;" ::: "memory");
        }

        // ---- encoder GEMV: z[r][tid] = relu(dot(w_tid, x_r) + b) ----
        {
            const ulonglong2* xsu = reinterpret_cast<const ulonglong2*>(xsA);
            #pragma unroll
            for (int rb = 0; rb < CHUNK; rb += 4) {
                ull a0 = 0, a1 = 0, a2 = 0, a3 = 0;
                #pragma unroll
                for (int g = 0; g < 16; g++) {
                    ulonglong2 x0 = xsu[(rb + 0) * 16 + g];
                    ulonglong2 x1 = xsu[(rb + 1) * 16 + g];
                    ulonglong2 x2 = xsu[(rb + 2) * 16 + g];
                    ulonglong2 x3 = xsu[(rb + 3) * 16 + g];
                    a0 = fma2(w2[2 * g], x0.x, a0); a0 = fma2(w2[2 * g + 1], x0.y, a0);
                    a1 = fma2(w2[2 * g], x1.x, a1); a1 = fma2(w2[2 * g + 1], x1.y, a1);
                    a2 = fma2(w2[2 * g], x2.x, a2); a2 = fma2(w2[2 * g + 1], x2.y, a2);
                    a3 = fma2(w2[2 * g], x3.x, a3); a3 = fma2(w2[2 * g + 1], x3.y, a3);
                }
                float lo, hi;
                unpack2(a0, lo, hi); zshA[(rb + 0) * LATENT + tid] = fmaxf(lo + hi + bl, 0.0f);
                unpack2(a1, lo, hi); zshA[(rb + 1) * LATENT + tid] = fmaxf(lo + hi + bl, 0.0f);
                unpack2(a2, lo, hi); zshA[(rb + 2) * LATENT + tid] = fmaxf(lo + hi + bl, 0.0f);
                unpack2(a3, lo, hi); zshA[(rb + 3) * LATENT + tid] = fmaxf(lo + hi + bl, 0.0f);
            }
        }
        __syncthreads();   // zsh(c) complete -> topk may read any latent

        // ---- per-warp: exact top-32 of row `wid`, z_sparse write, decode ----
        {
            const int r = wid;
            const long long row = row0 + r;

            // element (q,i) of this lane has latent index 128*q + 4*lane + i
            float va[16];
            {
                const float4* zr = reinterpret_cast<const float4*>(zshA + r * LATENT);
                #pragma unroll
                for (int q = 0; q < 4; q++) {
                    float4 t = zr[lane + 32 * q];
                    va[4 * q + 0] = t.x; va[4 * q + 1] = t.y;
                    va[4 * q + 2] = t.z; va[4 * q + 3] = t.w;
                }
            }

            // stats: sum (shfl tree) for warm start, max via REDUX
            float s = 0.0f, lmx = 0.0f;
            #pragma unroll
            for (int j = 0; j < 16; j++) { s += va[j]; lmx = fmaxf(lmx, va[j]); }
            unsigned mxu = __reduce_max_sync(FULL, __float_as_uint(lmx));
            #pragma unroll
            for (int off = 16; off > 0; off >>= 1)
                s += __shfl_xor_sync(FULL, s, off);

            unsigned T;        // bit pattern of 32nd-largest value
            unsigned ge_cnt;   // count(v >= T)

            if (mxu == 0u) {
                T = 0u; ge_cnt = 512u;
            } else {
                unsigned lo = 0u, hi = mxu + 1u;
                unsigned lo_c = 512u, hi_c = 0u;
                float sigma = (s * (1.0f / 512.0f)) * 2.5066283f;
                unsigned m = __float_as_uint(1.5341f * sigma);
                if (m <= lo) m = lo + 1u;
                if (m >= hi) m = hi - 1u;

                int iter = 0;
                T = 0u; ge_cnt = 512u;
                while (true) {
                    int cgt = 0;
                    #pragma unroll
                    for (int j = 0; j < 16; j++) cgt += (__float_as_uint(va[j]) >= m);
                    cgt = __reduce_add_sync(FULL, cgt);

                    if (cgt == KSEL) {
                        unsigned tmin = 0xffffffffu;
                        #pragma unroll
                        for (int j = 0; j < 16; j++) {
                            unsigned u = __float_as_uint(va[j]);
                            if (u >= m) tmin = min(tmin, u);
                        }
                        T = __reduce_min_sync(FULL, tmin);
                        ge_cnt = KSEL;
                        break;
                    }
                    if (cgt > KSEL) { lo = m; lo_c = (unsigned)cgt; }
                    else            { hi = m; hi_c = (unsigned)cgt; }
                    if (hi - lo <= 1u) { T = lo; ge_cnt = lo_c; break; }

                    iter++;
                    if (iter & 1) {
                        m = lo + ((hi - lo) >> 1);
                    } else {
                        float fl = __uint_as_float(lo), fh = __uint_as_float(hi);
                        float lc = __logf((float)lo_c);
                        float hc = __logf((float)max(hi_c, 1u));
                        float t  = (lc - 3.4657359f) / fmaxf(lc - hc, 1e-6f);
                        float mf = fl + t * (fh - fl);
                        unsigned mm = __float_as_uint(mf);
                        if (!(mf > fl && mf < fh)) mm = lo + ((hi - lo) >> 1);
                        m = mm;
                        if (m <= lo) m = lo + 1u;
                        if (m >= hi) m = hi - 1u;
                    }
                }
            }

            // ---- selection mask (stable ties, matching jax.lax.top_k) ----
            unsigned selmask = 0u;
            if (ge_cnt == KSEL) {
                #pragma unroll
                for (int j = 0; j < 16; j++)
                    if (__float_as_uint(va[j]) >= T) selmask |= 1u << j;
            } else {
                int gt = 0;
                #pragma unroll
                for (int j = 0; j < 16; j++) gt += (__float_as_uint(va[j]) > T);
                gt = __reduce_add_sync(FULL, gt);
                int need = KSEL - gt;
                int running = 0;
                #pragma unroll
                for (int j = 0; j < 16; j++) {
                    unsigned u = __float_as_uint(va[j]);
                    bool g = (u > T);
                    bool e = (u == T);
                    unsigned eb = __ballot_sync(FULL, e);
                    int rank = running + __popc(eb & ltmask);
                    running += __popc(eb);
                    if (g || (e && rank < need)) selmask |= 1u << j;
                }
            }

            // ---- z_sparse row: 4 coalesced STG.128 per lane ----
            {
                float4* oz = reinterpret_cast<float4*>(outz + row * LATENT);
                #pragma unroll
                for (int q = 0; q < 4; q++) {
                    float4 o;
                    o.x = ((selmask >> (4 * q + 0)) & 1u) ? va[4 * q + 0] : 0.0f;
                    o.y = ((selmask >> (4 * q + 1)) & 1u) ? va[4 * q + 1] : 0.0f;
                    o.z = ((selmask >> (4 * q + 2)) & 1u) ? va[4 * q + 2] : 0.0f;
                    o.w = ((selmask >> (4 * q + 3)) & 1u) ? va[4 * q + 3] : 0.0f;
                    oz[lane + 32 * q] = o;
                }
            }

            // ---- compact 32 selected (idx,val) pairs into SMEM ----
            ull* zs = zsel + r * KSEL;
            {
                unsigned running = 0;
                #pragma unroll
                for (int j = 0; j < 16; j++) {
                    bool sel = (selmask >> j) & 1u;
                    unsigned bal = __ballot_sync(FULL, sel);
                    if (sel) {
                        int slot = running + __popc(bal & ltmask);
                        int idx  = 128 * (j >> 2) + 4 * lane + (j & 3);
                        zs[slot] = ((ull)(unsigned)idx << 32) | (ull)__float_as_uint(va[j]);
                    }
                    running += __popc(bal);
                }
            }
            __syncwarp();

            // ---- decode: 32-step loop, 4 independent f32x2 accumulators ----
            ull acc0 = pack2(db0, db1), acc1 = 0, acc2 = 0, acc3 = 0;
            #pragma unroll
            for (int s4 = 0; s4 < KSEL; s4 += 4) {
                ulonglong2 p01 = *reinterpret_cast<const ulonglong2*>(zs + s4);
                ulonglong2 p23 = *reinterpret_cast<const ulonglong2*>(zs + s4 + 2);
                {
                    unsigned idx = (unsigned)(p01.x >> 32); float v = __uint_as_float((unsigned)p01.x);
                    ull dp = *reinterpret_cast<const ull*>(decT + idx * DEC_STRIDE + 2 * lane);
                    acc0 = fma2(pack2(v, v), dp, acc0);
                }
                {
                    unsigned idx = (unsigned)(p01.y >> 32); float v = __uint_as_float((unsigned)p01.y);
                    ull dp = *reinterpret_cast<const ull*>(decT + idx * DEC_STRIDE + 2 * lane);
                    acc1 = fma2(pack2(v, v), dp, acc1);
                }
                {
                    unsigned idx = (unsigned)(p23.x >> 32); float v = __uint_as_float((unsigned)p23.x);
                    ull dp = *reinterpret_cast<const ull*>(decT + idx * DEC_STRIDE + 2 * lane);
                    acc2 = fma2(pack2(v, v), dp, acc2);
                }
                {
                    unsigned idx = (unsigned)(p23.y >> 32); float v = __uint_as_float((unsigned)p23.y);
                    ull dp = *reinterpret_cast<const ull*>(decT + idx * DEC_STRIDE + 2 * lane);
                    acc3 = fma2(pack2(v, v), dp, acc3);
                }
            }
            acc0 = add2(add2(acc0, acc1), add2(acc2, acc3));
            float o0, o1;
            unpack2(acc0, o0, o1);
            float2 ov; ov.x = o0; ov.y = o1;
            *reinterpret_cast<float2*>(outx + row * D_IN + 2 * lane) = ov;
        }

        buf ^= 1;   // per-iteration toggle (fixes the GRID-even parity bug)
        // NO trailing barrier: next iteration's top barrier provides all ordering.
    }
}

extern "C" void kernel_launch(void* const* d_in, const int* in_sizes, int n_in,
                              void* d_out, int out_size)
{
    const float* x    = (const float*)d_in[0];
    const float* encW = (const float*)d_in[1];
    const float* encb = (const float*)d_in[2];
    const float* decW = (const float*)d_in[3];
    const float* decb = (const float*)d_in[4];

    const int B = in_sizes[0] / D_IN;
    float* outx = (float*)d_out;                       // x_hat [B, 64]
    float* outz = (float*)d_out + (size_t)B * D_IN;    // z_sparse [B, 512]

    const int nChunks = B / CHUNK;
    const size_t shmem = (size_t)SM_FLOATS * sizeof(float);   // 212992 B

    cudaFuncSetAttribute(sae_fused_kernel, cudaFuncAttributeMaxDynamicSharedMemorySize, (int)shmem);

    sae_fused_kernel<<<GRID, NTHREADS, shmem>>>(x, encW, encb, decW, decb, outx, outz, nChunks);
}

// round 4
// speedup vs baseline: 1.3191x; 1.0535x over previous
#include <cuda_runtime.h>
#include <cstdint>

#define D_IN      64
#define LATENT    512
#define KSEL      32
#define CHUNK     32
#define NTHREADS  512
#define DEC_STRIDE 64    // all decode lanes read the SAME decT row -> consecutive = conflict-free
#define GRID      152

typedef unsigned long long ull;

__device__ __forceinline__ ull pack2(float lo, float hi) {
    ull r; asm("mov.b64 %0, {%1,%2};" : "=l"(r) : "f"(lo), "f"(hi)); return r;
}
__device__ __forceinline__ void unpack2(ull v, float& lo, float& hi) {
    asm("mov.b64 {%0,%1}, %2;" : "=f"(lo), "=f"(hi) : "l"(v));
}
__device__ __forceinline__ ull fma2(ull a, ull b, ull c) {
    ull d; asm("fma.rn.f32x2 %0, %1, %2, %3;" : "=l"(d) : "l"(a), "l"(b), "l"(c)); return d;
}
__device__ __forceinline__ ull add2(ull a, ull b) {
    ull d; asm("add.rn.f32x2 %0, %1, %2;" : "=l"(d) : "l"(a), "l"(b)); return d;
}
__device__ __forceinline__ unsigned smem_u32(const void* p) {
    unsigned a; asm("{ .reg .u64 t; cvta.to.shared.u64 t, %1; cvt.u32.u64 %0, t; }" : "=r"(a) : "l"(p));
    return a;
}
__device__ __forceinline__ void cp_async16(unsigned dst, const void* src) {
    asm volatile("cp.async.ca.shared.global [%0], [%1], 16;" :: "r"(dst), "l"(src) : "memory");
}

// SMEM layout (float offsets):
//  decT : LATENT*64            = 32768 floats (131072 B)
//  zsh  : CHUNK*LATENT         = 16384 floats ( 65536 B)  single buffer
//  xs   : 2 * CHUNK*D_IN       =  4096 floats ( 16384 B)  double buffer
//  zsel : CHUNK*KSEL ulls      =  2048 floats (  8192 B)
//  total 221184 B
#define SM_DECT  0
#define SM_ZSH   (LATENT * DEC_STRIDE)
#define SM_XS    (SM_ZSH + CHUNK * LATENT)
#define SM_ZSEL  (SM_XS + 2 * CHUNK * D_IN)
#define SM_FLOATS (SM_ZSEL + 2 * CHUNK * KSEL)

__global__ void __launch_bounds__(NTHREADS, 1)
sae_fused_kernel(const float* __restrict__ x,
                 const float* __restrict__ encW,
                 const float* __restrict__ encb,
                 const float* __restrict__ decW,
                 const float* __restrict__ decb,
                 float* __restrict__ outx,
                 float* __restrict__ outz,
                 int nChunks)
{
    extern __shared__ float smem[];
    float* decT = smem + SM_DECT;
    float* zsh  = smem + SM_ZSH;
    float* xs   = smem + SM_XS;
    ull*   zsel = reinterpret_cast<ull*>(smem + SM_ZSEL);

    const int tid  = threadIdx.x;
    const int lane = tid & 31;
    const int wid  = tid >> 5;
    const unsigned FULL = 0xffffffffu;
    const unsigned ltmask = (1u << lane) - 1u;

    // ---- one-time: transpose dec_W [64,512] -> decT[l][d] ----
    for (int i = tid; i < D_IN * LATENT; i += NTHREADS) {
        int d = i >> 9;
        int l = i & (LATENT - 1);
        decT[l * DEC_STRIDE + d] = decW[i];
    }

    // ---- one-time: encoder weight row (latent = tid) into f32x2 registers ----
    ull w2[32];
    {
        const float4* wr = reinterpret_cast<const float4*>(encW + tid * D_IN);
        #pragma unroll
        for (int g = 0; g < 16; g++) {
            float4 v = wr[g];
            w2[2 * g]     = pack2(v.x, v.y);
            w2[2 * g + 1] = pack2(v.z, v.w);
        }
    }
    const float bl  = encb[tid];
    const float db0 = decb[2 * lane];
    const float db1 = decb[2 * lane + 1];

    unsigned Tprev = 0u;   // per-warp warm start for the threshold search

    // ---- prefetch x for first chunk into xs buffer 0 ----
    int c0 = blockIdx.x;
    int buf = 0;
    if (c0 < nChunks) {
        unsigned dst = smem_u32(xs) + tid * 16;
        cp_async16(dst, x + (long long)c0 * (CHUNK * D_IN) + tid * 4);
    }
    asm volatile("cp.async.commit_group;" ::: "memory");

    for (int c = c0; c < nChunks; c += GRID) {
        const long long row0 = (long long)c * CHUNK;
        float* xsA = xs + buf * (CHUNK * D_IN);

        // wait x(c); barrier also guarantees all topk(c-1) reads of zsh done
        asm volatile("cp.async.wait_group 0;" ::: "memory");
        __syncthreads();

        // prefetch chunk c+GRID into the other xs buffer (overlaps enc+topk)
        {
            int cn = c + GRID;
            if (cn < nChunks) {
                unsigned dst = smem_u32(xs + (buf ^ 1) * (CHUNK * D_IN)) + tid * 16;
                cp_async16(dst, x + (long long)cn * (CHUNK * D_IN) + tid * 4);
            }
            asm volatile("cp.async.commit_group;" ::: "memory");
        }

        // ---- encoder GEMV over 32 rows: z[r][tid] = relu(dot(w_tid, x_r)+b) ----
        {
            const ulonglong2* xsu = reinterpret_cast<const ulonglong2*>(xsA);
            #pragma unroll
            for (int rb = 0; rb < CHUNK; rb += 4) {
                ull a0 = 0, a1 = 0, a2 = 0, a3 = 0;
                #pragma unroll
                for (int g = 0; g < 16; g++) {
                    ulonglong2 x0 = xsu[(rb + 0) * 16 + g];
                    ulonglong2 x1 = xsu[(rb + 1) * 16 + g];
                    ulonglong2 x2 = xsu[(rb + 2) * 16 + g];
                    ulonglong2 x3 = xsu[(rb + 3) * 16 + g];
                    a0 = fma2(w2[2 * g], x0.x, a0); a0 = fma2(w2[2 * g + 1], x0.y, a0);
                    a1 = fma2(w2[2 * g], x1.x, a1); a1 = fma2(w2[2 * g + 1], x1.y, a1);
                    a2 = fma2(w2[2 * g], x2.x, a2); a2 = fma2(w2[2 * g + 1], x2.y, a2);
                    a3 = fma2(w2[2 * g], x3.x, a3); a3 = fma2(w2[2 * g + 1], x3.y, a3);
                }
                float lo, hi;
                unpack2(a0, lo, hi); zsh[(rb + 0) * LATENT + tid] = fmaxf(lo + hi + bl, 0.0f);
                unpack2(a1, lo, hi); zsh[(rb + 1) * LATENT + tid] = fmaxf(lo + hi + bl, 0.0f);
                unpack2(a2, lo, hi); zsh[(rb + 2) * LATENT + tid] = fmaxf(lo + hi + bl, 0.0f);
                unpack2(a3, lo, hi); zsh[(rb + 3) * LATENT + tid] = fmaxf(lo + hi + bl, 0.0f);
            }
        }
        __syncthreads();   // zsh complete -> topk may read any latent

        // ---- per-warp: rows wid and wid+16 ----
        #pragma unroll
        for (int half = 0; half < 2; half++) {
            const int r = wid + 16 * half;
            const long long row = row0 + r;

            float va[16];
            {
                const float4* zr = reinterpret_cast<const float4*>(zsh + r * LATENT);
                #pragma unroll
                for (int q = 0; q < 4; q++) {
                    float4 t = zr[lane + 32 * q];
                    va[4 * q + 0] = t.x; va[4 * q + 1] = t.y;
                    va[4 * q + 2] = t.z; va[4 * q + 3] = t.w;
                }
            }

            float lmx = 0.0f;
            #pragma unroll
            for (int j = 0; j < 16; j++) lmx = fmaxf(lmx, va[j]);
            unsigned mxu = __reduce_max_sync(FULL, __float_as_uint(lmx));

            unsigned T;        // bit pattern of 32nd-largest value
            unsigned ge_cnt;   // count(v >= T)

            if (mxu == 0u) {
                T = 0u; ge_cnt = 512u;
            } else {
                unsigned lo = 0u, hi = mxu + 1u;
                unsigned lo_c = 512u, hi_c = 0u;
                // warm start: previous row's threshold (iid rows -> close bit pattern)
                unsigned m = Tprev;
                if (m <= lo || m >= hi) m = lo + ((hi - lo) >> 1);

                int iter = 0;
                T = 0u; ge_cnt = 512u;
                while (true) {
                    int cgt = 0;
                    #pragma unroll
                    for (int j = 0; j < 16; j++) cgt += (__float_as_uint(va[j]) >= m);
                    cgt = __reduce_add_sync(FULL, cgt);

                    if (cgt == KSEL) {
                        unsigned tmin = 0xffffffffu;
                        #pragma unroll
                        for (int j = 0; j < 16; j++) {
                            unsigned u = __float_as_uint(va[j]);
                            if (u >= m) tmin = min(tmin, u);
                        }
                        T = __reduce_min_sync(FULL, tmin);
                        ge_cnt = KSEL;
                        break;
                    }
                    if (cgt > KSEL) { lo = m; lo_c = (unsigned)cgt; }
                    else            { hi = m; hi_c = (unsigned)cgt; }
                    if (hi - lo <= 1u) { T = lo; ge_cnt = lo_c; break; }

                    iter++;
                    if (iter & 1) {
                        m = lo + ((hi - lo) >> 1);
                    } else {
                        float fl = __uint_as_float(lo), fh = __uint_as_float(hi);
                        float lc = __logf((float)lo_c);
                        float hc = __logf((float)max(hi_c, 1u));
                        float t  = (lc - 3.4657359f) / fmaxf(lc - hc, 1e-6f);
                        float mf = fl + t * (fh - fl);
                        unsigned mm = __float_as_uint(mf);
                        if (!(mf > fl && mf < fh)) mm = lo + ((hi - lo) >> 1);
                        m = mm;
                        if (m <= lo) m = lo + 1u;
                        if (m >= hi) m = hi - 1u;
                    }
                }
                Tprev = T;
            }

            // ---- selection mask (stable ties, matching jax.lax.top_k) ----
            unsigned selmask = 0u;
            if (ge_cnt == KSEL) {
                #pragma unroll
                for (int j = 0; j < 16; j++)
                    if (__float_as_uint(va[j]) >= T) selmask |= 1u << j;
            } else {
                int gt = 0;
                #pragma unroll
                for (int j = 0; j < 16; j++) gt += (__float_as_uint(va[j]) > T);
                gt = __reduce_add_sync(FULL, gt);
                int need = KSEL - gt;
                int running = 0;
                #pragma unroll
                for (int j = 0; j < 16; j++) {
                    unsigned u = __float_as_uint(va[j]);
                    bool g = (u > T);
                    bool e = (u == T);
                    unsigned eb = __ballot_sync(FULL, e);
                    int rank = running + __popc(eb & ltmask);
                    running += __popc(eb);
                    if (g || (e && rank < need)) selmask |= 1u << j;
                }
            }

            // ---- z_sparse row: 4 coalesced STG.128 per lane ----
            {
                float4* oz = reinterpret_cast<float4*>(outz + row * LATENT);
                #pragma unroll
                for (int q = 0; q < 4; q++) {
                    float4 o;
                    o.x = ((selmask >> (4 * q + 0)) & 1u) ? va[4 * q + 0] : 0.0f;
                    o.y = ((selmask >> (4 * q + 1)) & 1u) ? va[4 * q + 1] : 0.0f;
                    o.z = ((selmask >> (4 * q + 2)) & 1u) ? va[4 * q + 2] : 0.0f;
                    o.w = ((selmask >> (4 * q + 3)) & 1u) ? va[4 * q + 3] : 0.0f;
                    oz[lane + 32 * q] = o;
                }
            }

            // ---- compact 32 selected (idx,val) pairs into SMEM ----
            ull* zs = zsel + r * KSEL;
            {
                unsigned running = 0;
                #pragma unroll
                for (int j = 0; j < 16; j++) {
                    bool sel = (selmask >> j) & 1u;
                    unsigned bal = __ballot_sync(FULL, sel);
                    if (sel) {
                        int slot = running + __popc(bal & ltmask);
                        int idx  = 128 * (j >> 2) + 4 * lane + (j & 3);
                        zs[slot] = ((ull)(unsigned)idx << 32) | (ull)__float_as_uint(va[j]);
                    }
                    running += __popc(bal);
                }
            }
            __syncwarp();

            // ---- decode: 32 steps, 4 independent f32x2 accumulators ----
            ull acc0 = pack2(db0, db1), acc1 = 0, acc2 = 0, acc3 = 0;
            #pragma unroll
            for (int s4 = 0; s4 < KSEL; s4 += 4) {
                ulonglong2 p01 = *reinterpret_cast<const ulonglong2*>(zs + s4);
                ulonglong2 p23 = *reinterpret_cast<const ulonglong2*>(zs + s4 + 2);
                {
                    unsigned idx = (unsigned)(p01.x >> 32); float v = __uint_as_float((unsigned)p01.x);
                    ull dp = *reinterpret_cast<const ull*>(decT + idx * DEC_STRIDE + 2 * lane);
                    acc0 = fma2(pack2(v, v), dp, acc0);
                }
                {
                    unsigned idx = (unsigned)(p01.y >> 32); float v = __uint_as_float((unsigned)p01.y);
                    ull dp = *reinterpret_cast<const ull*>(decT + idx * DEC_STRIDE + 2 * lane);
                    acc1 = fma2(pack2(v, v), dp, acc1);
                }
                {
                    unsigned idx = (unsigned)(p23.x >> 32); float v = __uint_as_float((unsigned)p23.x);
                    ull dp = *reinterpret_cast<const ull*>(decT + idx * DEC_STRIDE + 2 * lane);
                    acc2 = fma2(pack2(v, v), dp, acc2);
                }
                {
                    unsigned idx = (unsigned)(p23.y >> 32); float v = __uint_as_float((unsigned)p23.y);
                    ull dp = *reinterpret_cast<const ull*>(decT + idx * DEC_STRIDE + 2 * lane);
                    acc3 = fma2(pack2(v, v), dp, acc3);
                }
            }
            acc0 = add2(add2(acc0, acc1), add2(acc2, acc3));
            float o0, o1;
            unpack2(acc0, o0, o1);
            float2 ov; ov.x = o0; ov.y = o1;
            *reinterpret_cast<float2*>(outx + row * D_IN + 2 * lane) = ov;
        }

        buf ^= 1;
        // no trailing barrier: next iteration's top barrier provides all ordering
    }
}

extern "C" void kernel_launch(void* const* d_in, const int* in_sizes, int n_in,
                              void* d_out, int out_size)
{
    const float* x    = (const float*)d_in[0];
    const float* encW = (const float*)d_in[1];
    const float* encb = (const float*)d_in[2];
    const float* decW = (const float*)d_in[3];
    const float* decb = (const float*)d_in[4];

    const int B = in_sizes[0] / D_IN;
    float* outx = (float*)d_out;                       // x_hat [B, 64]
    float* outz = (float*)d_out + (size_t)B * D_IN;    // z_sparse [B, 512]

    const int nChunks = B / CHUNK;
    const size_t shmem = (size_t)SM_FLOATS * sizeof(float);   // 221184 B

    cudaFuncSetAttribute(sae_fused_kernel, cudaFuncAttributeMaxDynamicSharedMemorySize, (int)shmem);

    sae_fused_kernel<<<GRID, NTHREADS, shmem>>>(x, encW, encb, decW, decb, outx, outz, nChunks);
}